// round 1
// baseline (speedup 1.0000x reference)
#include <cuda_runtime.h>
#include <cuda_bf16.h>

#define DIM      4096
#define THREADS  256
#define EPT      16            // elements per thread
#define SMEM_FLOATS (DIM + (DIM >> 4))   // pad 1 float per 16 -> 4352 floats (17408 B)

__device__ __forceinline__ void fwht16(float v[EPT]) {
#pragma unroll
    for (int h = 1; h < EPT; h <<= 1) {
#pragma unroll
        for (int i = 0; i < EPT; i++) {
            if ((i & h) == 0) {
                float a = v[i];
                float b = v[i | h];
                v[i]     = a + b;
                v[i | h] = a - b;
            }
        }
    }
}

__global__ __launch_bounds__(THREADS)
void fwht4096_kernel(const float* __restrict__ x, float* __restrict__ y) {
    __shared__ float s[SMEM_FLOATS];

    const int row = blockIdx.x;
    const float* __restrict__ xr = x + (size_t)row * DIM;
    float* __restrict__       yr = y + (size_t)row * DIM;
    const int t = threadIdx.x;

    float v[EPT];

    // ---- Phase A: bits 0-3 (thread t owns contiguous elements [16t, 16t+16)) ----
    const float4* __restrict__ x4 = reinterpret_cast<const float4*>(xr) + t * 4;
#pragma unroll
    for (int j = 0; j < 4; j++) {
        float4 f = x4[j];
        v[4 * j + 0] = f.x;
        v[4 * j + 1] = f.y;
        v[4 * j + 2] = f.z;
        v[4 * j + 3] = f.w;
    }
    fwht16(v);

    // smem write: element i at phys = i + (i>>4).  Here i = 16t + j -> phys = 17t + j
    {
        float* sp = s + 17 * t;
#pragma unroll
        for (int j = 0; j < EPT; j++) sp[j] = v[j];
    }
    __syncthreads();

    // ---- Phase B: bits 4-7 (i = t_high*256 + k*16 + t_low) ----
    const int t_low  = t & 15;
    const int t_high = t >> 4;
#pragma unroll
    for (int k = 0; k < EPT; k++) {
        int i = t_high * 256 + k * 16 + t_low;
        v[k] = s[i + (i >> 4)];
    }
    fwht16(v);
    // Per-thread read set == write set, and sets partition smem -> no sync needed here.
#pragma unroll
    for (int k = 0; k < EPT; k++) {
        int i = t_high * 256 + k * 16 + t_low;
        s[i + (i >> 4)] = v[k];
    }
    __syncthreads();

    // ---- Phase C: bits 8-11 (i = k*256 + t) ----
#pragma unroll
    for (int k = 0; k < EPT; k++) {
        int i = k * 256 + t;
        v[k] = s[i + (i >> 4)];
    }
    fwht16(v);

    // scale by 1/sqrt(4096) = 1/64, coalesced stores (32 consecutive lanes per k)
    const float scale = 0.015625f;
#pragma unroll
    for (int k = 0; k < EPT; k++) {
        yr[k * 256 + t] = v[k] * scale;
    }
}

extern "C" void kernel_launch(void* const* d_in, const int* in_sizes, int n_in,
                              void* d_out, int out_size) {
    const float* x = (const float*)d_in[0];
    float* y = (float*)d_out;
    int rows = in_sizes[0] / DIM;   // 4 * 2048 = 8192
    fwht4096_kernel<<<rows, THREADS>>>(x, y);
}

// round 2
// speedup vs baseline: 1.1453x; 1.1453x over previous
#include <cuda_runtime.h>
#include <cuda_bf16.h>

#define DIM      4096
#define THREADS  256
#define EPT      16

// XOR swizzle: makes all four smem access patterns bank-conflict-free,
// no padding needed (exact 4096-float array).
__device__ __forceinline__ int swz(int i) {
    return i ^ (((i >> 6) & 7) << 2) ^ ((i >> 5) & 3);
}

__device__ __forceinline__ void fwht16(float v[EPT]) {
#pragma unroll
    for (int h = 1; h < EPT; h <<= 1) {
#pragma unroll
        for (int i = 0; i < EPT; i++) {
            if ((i & h) == 0) {
                float a = v[i];
                float b = v[i | h];
                v[i]     = a + b;
                v[i | h] = a - b;
            }
        }
    }
}

__global__ __launch_bounds__(THREADS)
void fwht4096_kernel(const float* __restrict__ x, float* __restrict__ y) {
    __shared__ float s[DIM];

    const int row = blockIdx.x;
    const float* __restrict__ xr = x + (size_t)row * DIM;
    float* __restrict__       yr = y + (size_t)row * DIM;
    const int t = threadIdx.x;

    float v[EPT];

    // ---- Phase A: bits {b0,b1,b10,b11} ----
    // Thread t holds i = g*1024 + t*4 + c  (g = b11b10, c = b1b0).
    // LDG.128 instr g: warp reads words g*256 + t -> contiguous 512B. Fully coalesced.
    const float4* __restrict__ x4 = reinterpret_cast<const float4*>(xr);
#pragma unroll
    for (int g = 0; g < 4; g++) {
        float4 f = __ldcs(x4 + g * 256 + t);
        v[4 * g + 0] = f.x;
        v[4 * g + 1] = f.y;
        v[4 * g + 2] = f.z;
        v[4 * g + 3] = f.w;
    }
    fwht16(v);   // register bits r0,r1 -> b0,b1 ; r2,r3 -> b10,b11

    // smem write (conflict-free under swz)
#pragma unroll
    for (int g = 0; g < 4; g++) {
#pragma unroll
        for (int c = 0; c < 4; c++) {
            int i = g * 1024 + t * 4 + c;
            s[swz(i)] = v[4 * g + c];
        }
    }
    __syncthreads();

    // Common thread decomposition for phases B/C:
    const int e = t & 3;          // b1b0
    const int m = (t >> 2) & 15;  // mid bits
    const int d = t >> 6;         // b11b10

    // ---- Phase B: bits {b2..b5} ----
    // i = d*1024 + m*64 + k*4 + e, k = 0..15
    const int baseB = d * 1024 + m * 64 + e;
#pragma unroll
    for (int k = 0; k < EPT; k++) {
        v[k] = s[swz(baseB + k * 4)];
    }
    fwht16(v);   // register bits -> b2..b5
    // read set == write set per thread, sets partition smem -> no sync here
#pragma unroll
    for (int k = 0; k < EPT; k++) {
        s[swz(baseB + k * 4)] = v[k];
    }
    __syncthreads();

    // ---- Phase C: bits {b6..b9} ----
    // i = d*1024 + k*64 + m*4 + e, k = 0..15
    const int baseC = d * 1024 + m * 4 + e;
#pragma unroll
    for (int k = 0; k < EPT; k++) {
        v[k] = s[swz(baseC + k * 64)];
    }
    fwht16(v);   // register bits -> b6..b9

    // scale by 1/sqrt(4096) = 1/64; stores: lanes cover b0..b4 -> 128B coalesced
    const float scale = 0.015625f;
#pragma unroll
    for (int k = 0; k < EPT; k++) {
        __stcs(yr + baseC + k * 64, v[k] * scale);
    }
}

extern "C" void kernel_launch(void* const* d_in, const int* in_sizes, int n_in,
                              void* d_out, int out_size) {
    const float* x = (const float*)d_in[0];
    float* y = (float*)d_out;
    int rows = in_sizes[0] / DIM;   // 8192
    fwht4096_kernel<<<rows, THREADS>>>(x, y);
}